// round 1
// baseline (speedup 1.0000x reference)
#include <cuda_runtime.h>
#include <math.h>

#define NC 64      // coarse samples
#define NF 128     // fine samples
#define NS 192     // combined
#define T  128     // threads per block (one ray per block)

__global__ void __launch_bounds__(T) nerf_kernel(
    const float* __restrict__ ro,   // [N,3]
    const float* __restrict__ rd,   // [N,3]
    const float* __restrict__ cw,   // [N,NC]
    const float* __restrict__ ct,   // [N,NC]
    const float* __restrict__ uu,   // [N,NF]
    const float* __restrict__ col,  // [N,NS,3]
    const float* __restrict__ dens, // [N,NS,1]
    float* __restrict__ out,        // rgb[3N] | depth[N] | opacity[N] | fine_points[N*NS*3]
    int N)
{
    __shared__ float s_cdf[NC + 1];   // 65
    __shared__ float s_ct[NC];        // 64
    __shared__ float s_fine[NF];      // 128
    __shared__ float s_comb[NS];      // 192
    __shared__ float s_alpha[NS];     // 192
    __shared__ float s_P[2 * T];      // 256 (product-scan, padded)
    __shared__ float s_od[6];
    __shared__ float s_w0;
    __shared__ float s_tot;
    __shared__ float s_red[4 * 5];

    const int ray = blockIdx.x;
    const int tid = threadIdx.x;

    // ---- load origin/dir ----
    if (tid < 3)       s_od[tid] = ro[(size_t)ray * 3 + tid];
    else if (tid < 6)  s_od[tid] = rd[(size_t)ray * 3 + (tid - 3)];

    // ---- Phase A: weights -> normalized CDF (65 entries, cdf[0]=0) ----
    float wv = 0.f;
    if (tid < NC) {
        s_ct[tid] = ct[(size_t)ray * NC + tid];
        wv = cw[(size_t)ray * NC + tid] + 1e-5f;
        #pragma unroll
        for (int o = 1; o < 32; o <<= 1) {
            float tval = __shfl_up_sync(0xffffffffu, wv, o);
            if ((tid & 31) >= o) wv += tval;
        }
        if (tid == 31) s_w0 = wv;
    }
    __syncthreads();
    if (tid >= 32 && tid < 64) wv += s_w0;
    if (tid == 63) s_tot = wv;
    __syncthreads();
    if (tid < NC) {
        s_cdf[tid + 1] = wv * (1.0f / s_tot);
    }
    if (tid == 64) s_cdf[0] = 0.f;
    __syncthreads();

    // ---- Phase B: inverse-CDF fine sampling (1 u per thread) ----
    {
        float uj = uu[(size_t)ray * NF + tid];
        int lo = 0, hi = NC + 1;                 // searchsorted right over 65 entries
        while (lo < hi) {
            int mid = (lo + hi) >> 1;
            if (s_cdf[mid] <= uj) lo = mid + 1; else hi = mid;
        }
        int below = lo - 1; if (below > NC - 1) below = NC - 1; if (below < 0) below = 0;
        int above = lo;     if (above > NC - 1) above = NC - 1;
        float cb = s_cdf[below], ca = s_cdf[above];
        float tb = s_ct[below],  ta = s_ct[above];
        float dn = ca - cb;
        if (dn < 1e-5f) dn = 1.f;
        s_fine[tid] = tb + ((uj - cb) / dn) * (ta - tb);
    }
    __syncthreads();

    // ---- Phase C: bitonic sort of the 128 fine t-values ----
    for (int k = 2; k <= NF; k <<= 1) {
        for (int j = k >> 1; j > 0; j >>= 1) {
            int l = tid ^ j;
            if (l > tid) {
                float a = s_fine[tid], b = s_fine[l];
                bool asc = (tid & k) == 0;
                if ((a > b) == asc) { s_fine[tid] = b; s_fine[l] = a; }
            }
            __syncthreads();
        }
    }

    // ---- Phase D: merge sorted coarse (64) with sorted fine (128) -> combined (192) ----
    {   // fine element: position = j + |{coarse < f}|
        float f = s_fine[tid];
        int lo = 0, hi = NC;
        while (lo < hi) {
            int mid = (lo + hi) >> 1;
            if (s_ct[mid] < f) lo = mid + 1; else hi = mid;
        }
        s_comb[tid + lo] = f;
    }
    if (tid < NC) {  // coarse element: position = i + |{fine <= c}|
        float c = s_ct[tid];
        int lo = 0, hi = NF;
        while (lo < hi) {
            int mid = (lo + hi) >> 1;
            if (s_fine[mid] <= c) lo = mid + 1; else hi = mid;
        }
        s_comb[tid + lo] = c;
    }
    __syncthreads();

    // ---- Phase E: points out, dists, alpha ----
    float ox = s_od[0], oy = s_od[1], oz = s_od[2];
    float dx = s_od[3], dy = s_od[4], dz = s_od[5];
    float dnorm = sqrtf(dx * dx + dy * dy + dz * dz);

    const size_t fpBase = (size_t)5 * N + (size_t)ray * (NS * 3);
    #pragma unroll
    for (int s0 = 0; s0 < 2; s0++) {
        int s = tid + s0 * T;
        if (s < NS) {
            float tv = s_comb[s];
            out[fpBase + s * 3 + 0] = ox + dx * tv;
            out[fpBase + s * 3 + 1] = oy + dy * tv;
            out[fpBase + s * 3 + 2] = oz + dz * tv;
            float dist = (s < NS - 1) ? (s_comb[s + 1] - tv) : 1e10f;
            dist *= dnorm;
            float de = dens[(size_t)ray * NS + s];
            float a = 1.f - expf(-de * dist);
            s_alpha[s] = a;
            s_P[s] = 1.f - a + 1e-10f;
        } else {
            s_P[s] = 1.f;   // pad for the scan
        }
    }
    __syncthreads();

    // ---- Phase F: inclusive multiplicative scan over 256 slots (Hillis-Steele) ----
    #pragma unroll
    for (int off = 1; off < 2 * T; off <<= 1) {
        float v0 = s_P[tid];
        float m0 = (tid >= off) ? s_P[tid - off] : 1.f;
        int   i1 = tid + T;
        float v1 = s_P[i1];
        float m1 = (i1 >= off) ? s_P[i1 - off] : 1.f;
        __syncthreads();
        s_P[tid] = v0 * m0;
        s_P[i1]  = v1 * m1;
        __syncthreads();
    }

    // ---- Phase G: weights, rgb/depth/opacity reductions ----
    float ar = 0.f, ag = 0.f, ab = 0.f, ad = 0.f, ao = 0.f;
    #pragma unroll
    for (int s0 = 0; s0 < 2; s0++) {
        int s = tid + s0 * T;
        if (s < NS) {
            float trans = (s == 0) ? 1.f : s_P[s - 1];   // exclusive cumprod
            float w = s_alpha[s] * trans;
            size_t cb = (size_t)ray * (NS * 3) + (size_t)s * 3;
            ar += w * col[cb + 0];
            ag += w * col[cb + 1];
            ab += w * col[cb + 2];
            ad += w * s_comb[s];
            ao += w;
        }
    }
    #pragma unroll
    for (int o = 16; o > 0; o >>= 1) {
        ar += __shfl_down_sync(0xffffffffu, ar, o);
        ag += __shfl_down_sync(0xffffffffu, ag, o);
        ab += __shfl_down_sync(0xffffffffu, ab, o);
        ad += __shfl_down_sync(0xffffffffu, ad, o);
        ao += __shfl_down_sync(0xffffffffu, ao, o);
    }
    int warp = tid >> 5, lane = tid & 31;
    if (lane == 0) {
        s_red[warp * 5 + 0] = ar;
        s_red[warp * 5 + 1] = ag;
        s_red[warp * 5 + 2] = ab;
        s_red[warp * 5 + 3] = ad;
        s_red[warp * 5 + 4] = ao;
    }
    __syncthreads();
    if (tid == 0) {
        float r = 0, g = 0, b = 0, d = 0, op = 0;
        #pragma unroll
        for (int w2 = 0; w2 < 4; w2++) {
            r  += s_red[w2 * 5 + 0];
            g  += s_red[w2 * 5 + 1];
            b  += s_red[w2 * 5 + 2];
            d  += s_red[w2 * 5 + 3];
            op += s_red[w2 * 5 + 4];
        }
        out[(size_t)ray * 3 + 0] = r;
        out[(size_t)ray * 3 + 1] = g;
        out[(size_t)ray * 3 + 2] = b;
        out[(size_t)3 * N + ray] = d;
        out[(size_t)4 * N + ray] = op;
    }
}

extern "C" void kernel_launch(void* const* d_in, const int* in_sizes, int n_in,
                              void* d_out, int out_size)
{
    const float* ro  = (const float*)d_in[0];
    const float* rd  = (const float*)d_in[1];
    const float* cw  = (const float*)d_in[2];
    const float* ct  = (const float*)d_in[3];
    const float* uu  = (const float*)d_in[4];
    const float* col = (const float*)d_in[5];
    const float* de  = (const float*)d_in[6];
    int N = in_sizes[0] / 3;
    nerf_kernel<<<N, T>>>(ro, rd, cw, ct, uu, col, de, (float*)d_out, N);
}

// round 4
// speedup vs baseline: 1.1882x; 1.1882x over previous
#include <cuda_runtime.h>
#include <math.h>

#define NC 64      // coarse samples
#define NF 128     // fine samples
#define NS 192     // combined
#define T  128     // threads per block (one ray per block)

__global__ void __launch_bounds__(T) nerf_kernel(
    const float* __restrict__ ro,   // [N,3]
    const float* __restrict__ rd,   // [N,3]
    const float* __restrict__ cw,   // [N,NC]
    const float* __restrict__ ct,   // [N,NC]
    const float* __restrict__ uu,   // [N,NF]
    const float* __restrict__ col,  // [N,NS,3]
    const float* __restrict__ dens, // [N,NS,1]
    float* __restrict__ out,        // rgb[3N] | depth[N] | opacity[N] | fine_points[N*NS*3]
    int N)
{
    __shared__ float s_cdf[NC + 1];   // 65
    __shared__ float s_ct[NC];        // 64
    __shared__ float s_fine[NF];      // 128
    __shared__ float s_comb[NS];      // 192
    __shared__ float s_w[NS];         // 192 (weights)
    __shared__ float s_od[6];
    __shared__ float s_wtA[2];        // coarse-weight warp totals
    __shared__ float s_wt[4];         // scan chunk-1 warp totals
    __shared__ float s_wt2[2];        // scan chunk-2 warp totals
    __shared__ float s_red[4 * 5];

    const int ray  = blockIdx.x;
    const int tid  = threadIdx.x;
    const int lane = tid & 31;
    const int warp = tid >> 5;

    // ---- Phase A: origin/dir + coarse weights -> normalized CDF ----
    if (tid < 3)      s_od[tid] = ro[(size_t)ray * 3 + tid];
    else if (tid < 6) s_od[tid] = rd[(size_t)ray * 3 + (tid - 3)];

    float cv = 0.f;
    if (tid < NC) {                       // warps 0,1 fully active
        s_ct[tid] = ct[(size_t)ray * NC + tid];
        cv = cw[(size_t)ray * NC + tid] + 1e-5f;
        #pragma unroll
        for (int o = 1; o < 32; o <<= 1) {
            float t2 = __shfl_up_sync(0xffffffffu, cv, o);
            if (lane >= o) cv += t2;
        }
        if (lane == 31) s_wtA[warp] = cv;
    }
    __syncthreads();
    if (tid < NC) {
        float inv = __fdividef(1.0f, s_wtA[0] + s_wtA[1]);
        float add = (warp == 1) ? s_wtA[0] : 0.f;
        s_cdf[tid + 1] = (cv + add) * inv;
    }
    if (tid == NC) s_cdf[0] = 0.f;
    __syncthreads();

    // ---- Phase B: inverse-CDF fine sampling (register result) ----
    float v;
    {
        float uj = uu[(size_t)ray * NF + tid];
        int lo = 0, hi = NC + 1;                 // searchsorted right, 65 entries
        while (lo < hi) {
            int mid = (lo + hi) >> 1;
            if (s_cdf[mid] <= uj) lo = mid + 1; else hi = mid;
        }
        int below = lo - 1; if (below > NC - 1) below = NC - 1; if (below < 0) below = 0;
        int above = lo;     if (above > NC - 1) above = NC - 1;
        float cb = s_cdf[below], ca = s_cdf[above];
        float tb = s_ct[below],  ta = s_ct[above];
        float dn = ca - cb;
        if (dn < 1e-5f) dn = 1.f;
        v = tb + __fdividef(uj - cb, dn) * (ta - tb);
    }

    // ---- Phase C: bitonic sort of 128 fine values, register-resident ----
    #pragma unroll
    for (int k = 2; k <= NF; k <<= 1) {
        #pragma unroll
        for (int j = k >> 1; j > 0; j >>= 1) {
            float pv;
            if (j >= 32) {                       // cross-warp: via SMEM
                s_fine[tid] = v; __syncthreads();
                pv = s_fine[tid ^ j]; __syncthreads();
            } else {                             // in-warp: shuffle
                pv = __shfl_xor_sync(0xffffffffu, v, j);
            }
            bool up = ((tid & k) == 0);
            bool keepMin = (((tid & j) == 0) == up);
            v = keepMin ? fminf(v, pv) : fmaxf(v, pv);
        }
    }
    s_fine[tid] = v;
    __syncthreads();

    // ---- Phase D: merge sorted coarse(64) + sorted fine(128) -> comb(192) ----
    {   // fine element: pos = j + |{coarse < f}|
        int lo = 0, hi = NC;
        while (lo < hi) {
            int mid = (lo + hi) >> 1;
            if (s_ct[mid] < v) lo = mid + 1; else hi = mid;
        }
        s_comb[tid + lo] = v;
    }
    if (tid < NC) {  // coarse element: pos = i + |{fine <= c}|
        float c = s_ct[tid];
        int lo = 0, hi = NF;
        while (lo < hi) {
            int mid = (lo + hi) >> 1;
            if (s_fine[mid] <= c) lo = mid + 1; else hi = mid;
        }
        s_comb[tid + lo] = c;
    }
    __syncthreads();

    // ---- Phase E: alpha at s=tid (chunk1) and s=tid+128 (chunk2, tid<64) ----
    float dx = s_od[3], dy = s_od[4], dz = s_od[5];
    float dnorm = sqrtf(dx * dx + dy * dy + dz * dz);

    float tv0 = s_comb[tid];
    float nx0 = (tid < NS - 1 - NC) ? s_comb[tid + 1] : s_comb[tid + 1]; // tid+1 <= 128 valid
    float dist0 = (nx0 - tv0) * dnorm;
    float de0 = dens[(size_t)ray * NS + tid];
    float a0 = 1.f - __expf(-de0 * dist0);
    float p0 = 1.f - a0 + 1e-10f;

    float a1 = 0.f, tv1 = 0.f;
    float p1 = 1.f;
    if (tid < NC) {
        int s = tid + NF;                        // 128..191
        tv1 = s_comb[s];
        float dist1 = (s < NS - 1) ? (s_comb[s + 1] - tv1) * dnorm : 1e10f * dnorm;
        float de1 = dens[(size_t)ray * NS + s];
        a1 = 1.f - __expf(-de1 * dist1);
        p1 = 1.f - a1 + 1e-10f;
    }

    // ---- Phase F: transmittance via shuffle product-scans ----
    float sc0 = p0;
    #pragma unroll
    for (int o = 1; o < 32; o <<= 1) {
        float t2 = __shfl_up_sync(0xffffffffu, sc0, o);
        if (lane >= o) sc0 *= t2;
    }
    if (lane == 31) s_wt[warp] = sc0;

    float sc1 = p1;
    if (tid < NC) {                              // warps 0,1 fully active
        #pragma unroll
        for (int o = 1; o < 32; o <<= 1) {
            float t2 = __shfl_up_sync(0xffffffffu, sc1, o);
            if (lane >= o) sc1 *= t2;
        }
        if (lane == 31) s_wt2[warp] = sc1;
    }
    __syncthreads();

    float pref = 1.f;
    if (warp > 0) pref *= s_wt[0];
    if (warp > 1) pref *= s_wt[1];
    if (warp > 2) pref *= s_wt[2];
    float ex0 = __shfl_up_sync(0xffffffffu, sc0, 1);
    float trans0 = (lane == 0) ? pref : pref * ex0;
    float w0 = a0 * trans0;

    float ad = w0 * tv0;   // depth accum
    float ao = w0;         // opacity accum
    s_w[tid] = w0;

    if (tid < NC) {
        float T128 = s_wt[0] * s_wt[1] * s_wt[2] * s_wt[3];
        float pref1 = (warp == 1) ? T128 * s_wt2[0] : T128;
        float ex1 = __shfl_up_sync(0xffffffffu, sc1, 1);
        float trans1 = (lane == 0) ? pref1 : pref1 * ex1;
        float w1 = a1 * trans1;
        ad += w1 * tv1;
        ao += w1;
        s_w[tid + NF] = w1;
    }
    __syncthreads();

    // ---- Phase G: fused coalesced fine_points store + color accumulation ----
    float ox = s_od[0], oy = s_od[1], oz = s_od[2];
    const size_t fpBase = (size_t)5 * N + (size_t)ray * (NS * 3);
    const size_t cBase  = (size_t)ray * (NS * 3);
    float ar = 0.f, ag = 0.f, ab = 0.f;

    #pragma unroll
    for (int k = 0; k < 5; k++) {
        int i = tid + k * T;
        if (i < NS * 3) {
            int s = i / 3;
            int c = i - 3 * s;
            float tvs = s_comb[s];
            float oc = (c == 0) ? ox : ((c == 1) ? oy : oz);
            float dc = (c == 0) ? dx : ((c == 1) ? dy : dz);
            out[fpBase + i] = oc + dc * tvs;

            float contrib = s_w[s] * col[cBase + i];
            if (c == 0)      ar += contrib;
            else if (c == 1) ag += contrib;
            else             ab += contrib;
        }
    }

    // ---- reductions ----
    #pragma unroll
    for (int o = 16; o > 0; o >>= 1) {
        ar += __shfl_down_sync(0xffffffffu, ar, o);
        ag += __shfl_down_sync(0xffffffffu, ag, o);
        ab += __shfl_down_sync(0xffffffffu, ab, o);
        ad += __shfl_down_sync(0xffffffffu, ad, o);
        ao += __shfl_down_sync(0xffffffffu, ao, o);
    }
    if (lane == 0) {
        s_red[warp * 5 + 0] = ar;
        s_red[warp * 5 + 1] = ag;
        s_red[warp * 5 + 2] = ab;
        s_red[warp * 5 + 3] = ad;
        s_red[warp * 5 + 4] = ao;
    }
    __syncthreads();
    if (tid == 0) {
        float r = 0, g = 0, b = 0, d = 0, op = 0;
        #pragma unroll
        for (int w2 = 0; w2 < 4; w2++) {
            r  += s_red[w2 * 5 + 0];
            g  += s_red[w2 * 5 + 1];
            b  += s_red[w2 * 5 + 2];
            d  += s_red[w2 * 5 + 3];
            op += s_red[w2 * 5 + 4];
        }
        out[(size_t)ray * 3 + 0] = r;
        out[(size_t)ray * 3 + 1] = g;
        out[(size_t)ray * 3 + 2] = b;
        out[(size_t)3 * N + ray] = d;
        out[(size_t)4 * N + ray] = op;
    }
}

extern "C" void kernel_launch(void* const* d_in, const int* in_sizes, int n_in,
                              void* d_out, int out_size)
{
    const float* ro  = (const float*)d_in[0];
    const float* rd  = (const float*)d_in[1];
    const float* cw  = (const float*)d_in[2];
    const float* ct  = (const float*)d_in[3];
    const float* uu  = (const float*)d_in[4];
    const float* col = (const float*)d_in[5];
    const float* de  = (const float*)d_in[6];
    int N = in_sizes[0] / 3;
    nerf_kernel<<<N, T>>>(ro, rd, cw, ct, uu, col, de, (float*)d_out, N);
}

// round 7
// speedup vs baseline: 1.2959x; 1.0907x over previous
#include <cuda_runtime.h>
#include <math.h>

#define NC 64      // coarse samples
#define NF 128     // fine samples
#define NS 192     // combined
#define T  128     // threads per block (one ray per block)

__global__ void __launch_bounds__(T) nerf_kernel(
    const float* __restrict__ ro,   // [N,3]
    const float* __restrict__ rd,   // [N,3]
    const float* __restrict__ cw,   // [N,NC]
    const float* __restrict__ ct,   // [N,NC]
    const float* __restrict__ uu,   // [N,NF]
    const float* __restrict__ col,  // [N,NS,3]
    const float* __restrict__ dens, // [N,NS,1]
    float* __restrict__ out,        // rgb[3N] | depth[N] | opacity[N] | fine_points[N*NS*3]
    int N)
{
    __shared__ float  s_cdf[NC + 1];   // 65
    __shared__ float  s_ct[NC];        // 64
    __shared__ float  s_fine[NF];      // 128
    __shared__ float  s_comb[NS];      // 192
    __shared__ float2 s_wc[NS];        // 192 (t_val, weight) pairs
    __shared__ float  s_od[6];
    __shared__ float  s_wtA[2];
    __shared__ float  s_wt[4];
    __shared__ float  s_wt2[2];
    __shared__ float  s_red[4 * 5];

    const int ray  = blockIdx.x;
    const int tid  = threadIdx.x;
    const int lane = tid & 31;
    const int warp = tid >> 5;

    // ---- Phase A: origin/dir + coarse weights -> normalized CDF ----
    if (tid < 3)      s_od[tid] = ro[(size_t)ray * 3 + tid];
    else if (tid < 6) s_od[tid] = rd[(size_t)ray * 3 + (tid - 3)];

    float cv = 0.f;
    if (tid < NC) {                       // warps 0,1 fully active
        s_ct[tid] = ct[(size_t)ray * NC + tid];
        cv = cw[(size_t)ray * NC + tid] + 1e-5f;
        #pragma unroll
        for (int o = 1; o < 32; o <<= 1) {
            float t2 = __shfl_up_sync(0xffffffffu, cv, o);
            if (lane >= o) cv += t2;
        }
        if (lane == 31) s_wtA[warp] = cv;
    }
    __syncthreads();
    if (tid < NC) {
        float inv = __fdividef(1.0f, s_wtA[0] + s_wtA[1]);
        float add = (warp == 1) ? s_wtA[0] : 0.f;
        s_cdf[tid + 1] = (cv + add) * inv;
    }
    if (tid == NC) s_cdf[0] = 0.f;
    __syncthreads();

    // ---- Phase B: inverse-CDF fine sampling (register result) ----
    float v;
    {
        float uj = uu[(size_t)ray * NF + tid];
        // searchsorted-right over cdf[0..64]. cdf[0]=0 <= u always, so
        // lo = 1 + count{ cdf[1..64] <= u }. Branchless monobound count:
        const float* a = s_cdf + 1;        // length 64
        int base = 0;
        #pragma unroll
        for (int half = 32; half >= 1; half >>= 1)
            if (a[base + half - 1] <= uj) base += half;   // base <= 63 here
        if (a[base] <= uj) base += 1;      // final check, base <= 64
        int lo = 1 + base;
        int below = (base < NC) ? base : (NC - 1);        // clip(lo-1,0,63)
        int above = (lo   < NC) ? lo   : (NC - 1);        // clip(lo,  0,63)
        float cb = s_cdf[below], ca = s_cdf[above];
        float tb = s_ct[below],  ta = s_ct[above];
        float dn = ca - cb;
        if (dn < 1e-5f) dn = 1.f;
        v = tb + __fdividef(uj - cb, dn) * (ta - tb);
    }

    // ---- Phase C: bitonic sort of 128 fine values, register-resident ----
    #pragma unroll
    for (int k = 2; k <= NF; k <<= 1) {
        #pragma unroll
        for (int j = k >> 1; j > 0; j >>= 1) {
            float pv;
            if (j >= 32) {                       // cross-warp: via SMEM
                s_fine[tid] = v; __syncthreads();
                pv = s_fine[tid ^ j]; __syncthreads();
            } else {                             // in-warp: shuffle
                pv = __shfl_xor_sync(0xffffffffu, v, j);
            }
            bool up = ((tid & k) == 0);
            bool keepMin = (((tid & j) == 0) == up);
            v = keepMin ? fminf(v, pv) : fmaxf(v, pv);
        }
    }
    s_fine[tid] = v;
    __syncthreads();

    // ---- Phase D: merge sorted coarse(64) + sorted fine(128) -> comb(192) ----
    {   // fine element: pos = tid + count{ coarse < v }  (monobound, len 64)
        int base = 0;
        #pragma unroll
        for (int half = 32; half >= 1; half >>= 1)
            if (s_ct[base + half - 1] < v) base += half;
        if (s_ct[base < NC ? base : NC - 1] < v && base < NC) base += 1;
        s_comb[tid + base] = v;
    }
    if (tid < NC) {  // coarse element: pos = tid + count{ fine <= c }  (len 128)
        float c = s_ct[tid];
        int base = 0;
        #pragma unroll
        for (int half = 64; half >= 1; half >>= 1)
            if (s_fine[base + half - 1] <= c) base += half;
        if (base < NF && s_fine[base] <= c) base += 1;
        s_comb[tid + base] = c;
    }
    __syncthreads();

    // ---- Phase E: alpha at s=tid (chunk1) and s=tid+128 (chunk2, tid<64) ----
    float dx = s_od[3], dy = s_od[4], dz = s_od[5];
    float dnorm = sqrtf(dx * dx + dy * dy + dz * dz);

    float tv0 = s_comb[tid];
    float dist0 = (s_comb[tid + 1] - tv0) * dnorm;     // tid+1 <= 128, valid
    float de0 = dens[(size_t)ray * NS + tid];
    float a0 = 1.f - __expf(-de0 * dist0);
    float p0 = 1.f - a0 + 1e-10f;

    float a1 = 0.f, tv1 = 0.f;
    float p1 = 1.f;
    if (tid < NC) {
        int s = tid + NF;                        // 128..191
        tv1 = s_comb[s];
        float dist1 = (s < NS - 1) ? (s_comb[s + 1] - tv1) * dnorm : 1e10f * dnorm;
        float de1 = dens[(size_t)ray * NS + s];
        a1 = 1.f - __expf(-de1 * dist1);
        p1 = 1.f - a1 + 1e-10f;
    }

    // ---- Phase F: transmittance via shuffle product-scans ----
    float sc0 = p0;
    #pragma unroll
    for (int o = 1; o < 32; o <<= 1) {
        float t2 = __shfl_up_sync(0xffffffffu, sc0, o);
        if (lane >= o) sc0 *= t2;
    }
    if (lane == 31) s_wt[warp] = sc0;

    float sc1 = p1;
    if (tid < NC) {                              // warps 0,1 fully active
        #pragma unroll
        for (int o = 1; o < 32; o <<= 1) {
            float t2 = __shfl_up_sync(0xffffffffu, sc1, o);
            if (lane >= o) sc1 *= t2;
        }
        if (lane == 31) s_wt2[warp] = sc1;
    }
    __syncthreads();

    float pref = 1.f;
    if (warp > 0) pref *= s_wt[0];
    if (warp > 1) pref *= s_wt[1];
    if (warp > 2) pref *= s_wt[2];
    float ex0 = __shfl_up_sync(0xffffffffu, sc0, 1);
    float trans0 = (lane == 0) ? pref : pref * ex0;
    float w0 = a0 * trans0;

    float ad = w0 * tv0;   // depth accum
    float ao = w0;         // opacity accum
    s_wc[tid] = make_float2(tv0, w0);

    if (tid < NC) {
        float T128 = s_wt[0] * s_wt[1] * s_wt[2] * s_wt[3];
        float pref1 = (warp == 1) ? T128 * s_wt2[0] : T128;
        float ex1 = __shfl_up_sync(0xffffffffu, sc1, 1);
        float trans1 = (lane == 0) ? pref1 : pref1 * ex1;
        float w1 = a1 * trans1;
        ad += w1 * tv1;
        ao += w1;
        s_wc[tid + NF] = make_float2(tv1, w1);
    }
    __syncthreads();

    // ---- Phase G: float4 coalesced fine_points store + color accumulation ----
    float ox = s_od[0], oy = s_od[1], oz = s_od[2];
    const float4* col4 = reinterpret_cast<const float4*>(col + (size_t)ray * (NS * 3));
    float4*       out4 = reinterpret_cast<float4*>(out + (size_t)5 * N + (size_t)ray * (NS * 3));
    float ar = 0.f, ag = 0.f, ab = 0.f;

    #pragma unroll
    for (int k = 0; k < 2; k++) {
        int i4 = tid + k * T;
        if (i4 < (NS * 3) / 4) {                 // 144 float4s
            int e  = i4 * 4;
            int s0 = e / 3;
            int c0 = e - 3 * s0;
            float2 wcA = s_wc[s0];
            float2 wcB = s_wc[s0 + 1];           // s0 max = 190 -> safe
            float4 cvv = col4[i4];
            float ce[4] = {cvv.x, cvv.y, cvv.z, cvv.w};
            float pe[4];
            #pragma unroll
            for (int j = 0; j < 4; j++) {
                int c = c0 + j;
                float2 wc = wcA;
                if (c >= 3) { c -= 3; wc = wcB; }
                float oc = (c == 0) ? ox : ((c == 1) ? oy : oz);
                float dc = (c == 0) ? dx : ((c == 1) ? dy : dz);
                pe[j] = fmaf(dc, wc.x, oc);
                float contrib = wc.y * ce[j];
                if (c == 0)      ar += contrib;
                else if (c == 1) ag += contrib;
                else             ab += contrib;
            }
            out4[i4] = make_float4(pe[0], pe[1], pe[2], pe[3]);
        }
    }

    // ---- reductions ----
    #pragma unroll
    for (int o = 16; o > 0; o >>= 1) {
        ar += __shfl_down_sync(0xffffffffu, ar, o);
        ag += __shfl_down_sync(0xffffffffu, ag, o);
        ab += __shfl_down_sync(0xffffffffu, ab, o);
        ad += __shfl_down_sync(0xffffffffu, ad, o);
        ao += __shfl_down_sync(0xffffffffu, ao, o);
    }
    if (lane == 0) {
        s_red[warp * 5 + 0] = ar;
        s_red[warp * 5 + 1] = ag;
        s_red[warp * 5 + 2] = ab;
        s_red[warp * 5 + 3] = ad;
        s_red[warp * 5 + 4] = ao;
    }
    __syncthreads();
    if (tid == 0) {
        float r = 0, g = 0, b = 0, d = 0, op = 0;
        #pragma unroll
        for (int w2 = 0; w2 < 4; w2++) {
            r  += s_red[w2 * 5 + 0];
            g  += s_red[w2 * 5 + 1];
            b  += s_red[w2 * 5 + 2];
            d  += s_red[w2 * 5 + 3];
            op += s_red[w2 * 5 + 4];
        }
        out[(size_t)ray * 3 + 0] = r;
        out[(size_t)ray * 3 + 1] = g;
        out[(size_t)ray * 3 + 2] = b;
        out[(size_t)3 * N + ray] = d;
        out[(size_t)4 * N + ray] = op;
    }
}

extern "C" void kernel_launch(void* const* d_in, const int* in_sizes, int n_in,
                              void* d_out, int out_size)
{
    const float* ro  = (const float*)d_in[0];
    const float* rd  = (const float*)d_in[1];
    const float* cw  = (const float*)d_in[2];
    const float* ct  = (const float*)d_in[3];
    const float* uu  = (const float*)d_in[4];
    const float* col = (const float*)d_in[5];
    const float* de  = (const float*)d_in[6];
    int N = in_sizes[0] / 3;
    nerf_kernel<<<N, T>>>(ro, rd, cw, ct, uu, col, de, (float*)d_out, N);
}

// round 8
// speedup vs baseline: 2.4153x; 1.8637x over previous
#include <cuda_runtime.h>
#include <math.h>

#define NC 64      // coarse samples
#define NF 128     // fine samples
#define NS 192     // combined
#define RPB 4      // rays per block (one warp each)
#define T (32 * RPB)
#define FULL 0xffffffffu

struct alignas(16) RayShm {
    float2 wc[NS];                 // (t, w) per combined sample      1536 B
    union {
        struct {
            float fine[NF];        // offset 0 (16B aligned)
            float cdf[NC + 2];     // 66 (1 pad -> ct 8B aligned)
            float ct[NC];
        } a;                       // 258 floats
        float p[NS];               // overlays fine+cdf after D
    } u;                           // 1032 B
    float od[6];                   // origin xyz, dir xyz
    float pad[2];
};

// in-register compare-exchange
#define CEI(a, b, asc) { float lo_ = fminf(a, b), hi_ = fmaxf(a, b); \
                         a = (asc) ? lo_ : hi_; b = (asc) ? hi_ : lo_; }
// shuffle compare-exchange on all 4 regs, lane-distance d, direction up
#define CES(d, up) { bool km_ = (((l & (d)) == 0) == (up)); float pv_; \
    pv_ = __shfl_xor_sync(FULL, r0, (d)); r0 = km_ ? fminf(r0, pv_) : fmaxf(r0, pv_); \
    pv_ = __shfl_xor_sync(FULL, r1, (d)); r1 = km_ ? fminf(r1, pv_) : fmaxf(r1, pv_); \
    pv_ = __shfl_xor_sync(FULL, r2, (d)); r2 = km_ ? fminf(r2, pv_) : fmaxf(r2, pv_); \
    pv_ = __shfl_xor_sync(FULL, r3, (d)); r3 = km_ ? fminf(r3, pv_) : fmaxf(r3, pv_); }

__global__ void __launch_bounds__(T) nerf_kernel(
    const float* __restrict__ ro,   // [N,3]
    const float* __restrict__ rd,   // [N,3]
    const float* __restrict__ cw,   // [N,NC]
    const float* __restrict__ ct,   // [N,NC]
    const float* __restrict__ uu,   // [N,NF]
    const float* __restrict__ col,  // [N,NS,3]
    const float* __restrict__ dens, // [N,NS,1]
    float* __restrict__ out,        // rgb[3N] | depth[N] | opacity[N] | fine_points[N*NS*3]
    int N)
{
    __shared__ RayShm sh[RPB];
    const int warp = threadIdx.x >> 5;
    const int l    = threadIdx.x & 31;
    const int ray  = blockIdx.x * RPB + warp;
    if (ray >= N) return;
    RayShm& S = sh[warp];

    // ---- Phase A: origin/dir + coarse t + weights -> normalized CDF ----
    if (l < 3)      S.od[l] = ro[(size_t)ray * 3 + l];
    else if (l < 6) S.od[l] = rd[(size_t)ray * 3 + (l - 3)];

    {   // 2 elements per lane (2l, 2l+1), float2 coalesced
        float2 ctp = reinterpret_cast<const float2*>(ct + (size_t)ray * NC)[l];
        reinterpret_cast<float2*>(S.u.a.ct)[l] = ctp;
        float2 cwp = reinterpret_cast<const float2*>(cw + (size_t)ray * NC)[l];
        float e0 = cwp.x + 1e-5f, e1 = cwp.y + 1e-5f;
        float pairv = e0 + e1;
        float scn = pairv;
        #pragma unroll
        for (int o = 1; o < 32; o <<= 1) {
            float t2 = __shfl_up_sync(FULL, scn, o);
            if (l >= o) scn += t2;
        }
        float total = __shfl_sync(FULL, scn, 31);
        float inv = __fdividef(1.0f, total);
        float pre = scn - pairv;
        S.u.a.cdf[2 * l + 1] = (pre + e0) * inv;
        S.u.a.cdf[2 * l + 2] = scn * inv;
        if (l == 0) S.u.a.cdf[0] = 0.f;
    }
    __syncwarp();

    // ---- Phase B: 4 inverse-CDF samples per lane (cyclic), store to fine[] ----
    {
        const float* ub = uu + (size_t)ray * NF;
        #pragma unroll
        for (int s = 0; s < 4; s++) {
            float uj = ub[l + 32 * s];
            const float* a = S.u.a.cdf + 1;      // length 64
            int base = 0;
            #pragma unroll
            for (int half = 32; half >= 1; half >>= 1)
                if (a[base + half - 1] <= uj) base += half;   // base <= 63
            if (a[base] <= uj) base += 1;                     // base <= 64
            int lo = 1 + base;
            int below = (base < NC) ? base : (NC - 1);
            int above = (lo   < NC) ? lo   : (NC - 1);
            float cb = S.u.a.cdf[below], ca = S.u.a.cdf[above];
            float tb = S.u.a.ct[below],  ta = S.u.a.ct[above];
            float dn = ca - cb;
            if (dn < 1e-5f) dn = 1.f;
            S.u.a.fine[l + 32 * s] = tb + __fdividef(uj - cb, dn) * (ta - tb);
        }
    }
    __syncwarp();

    // ---- Phase C: bitonic sort, 4 elems/lane blocked (elements 4l..4l+3) ----
    float4 rr = reinterpret_cast<float4*>(S.u.a.fine)[l];
    float r0 = rr.x, r1 = rr.y, r2 = rr.z, r3 = rr.w;
    {
        // k=2
        CEI(r0, r1, true); CEI(r2, r3, false);
        // k=4
        { bool up = ((l & 1) == 0);
          CEI(r0, r2, up); CEI(r1, r3, up);
          CEI(r0, r1, up); CEI(r2, r3, up); }
        // k=8
        { bool up = ((l & 2) == 0);
          CES(1, up);
          CEI(r0, r2, up); CEI(r1, r3, up);
          CEI(r0, r1, up); CEI(r2, r3, up); }
        // k=16
        { bool up = ((l & 4) == 0);
          CES(2, up); CES(1, up);
          CEI(r0, r2, up); CEI(r1, r3, up);
          CEI(r0, r1, up); CEI(r2, r3, up); }
        // k=32
        { bool up = ((l & 8) == 0);
          CES(4, up); CES(2, up); CES(1, up);
          CEI(r0, r2, up); CEI(r1, r3, up);
          CEI(r0, r1, up); CEI(r2, r3, up); }
        // k=64
        { bool up = ((l & 16) == 0);
          CES(8, up); CES(4, up); CES(2, up); CES(1, up);
          CEI(r0, r2, up); CEI(r1, r3, up);
          CEI(r0, r1, up); CEI(r2, r3, up); }
        // k=128 (ascending)
        { CES(16, true); CES(8, true); CES(4, true); CES(2, true); CES(1, true);
          CEI(r0, r2, true); CEI(r1, r3, true);
          CEI(r0, r1, true); CEI(r2, r3, true); }
    }
    reinterpret_cast<float4*>(S.u.a.fine)[l] = make_float4(r0, r1, r2, r3);
    __syncwarp();

    // ---- Phase D: merge into wc[].x ----
    {   // fine elements: pos = (4l+s) + count{ coarse < v }
        float vv[4] = {r0, r1, r2, r3};
        #pragma unroll
        for (int s = 0; s < 4; s++) {
            float v = vv[s];
            int base = 0;
            #pragma unroll
            for (int half = 32; half >= 1; half >>= 1)
                if (S.u.a.ct[base + half - 1] < v) base += half;   // base <= 63
            if (base < NC) { if (S.u.a.ct[base] < v) base += 1; }
            S.wc[4 * l + s + base].x = v;
        }
        // coarse elements: pos = idx + count{ fine <= c }
        #pragma unroll
        for (int m = 0; m < 2; m++) {
            int idx = l + 32 * m;
            float c = S.u.a.ct[idx];
            int base = 0;
            #pragma unroll
            for (int half = 64; half >= 1; half >>= 1)
                if (S.u.a.fine[base + half - 1] <= c) base += half; // base <= 127
            if (base < NF) { if (S.u.a.fine[base] <= c) base += 1; }
            S.wc[idx + base].x = c;
        }
    }
    __syncwarp();

    // ---- Phase E: p = exp(-d*dist)+1e-10, cyclic 6/lane, into p[] overlay ----
    float dx = S.od[3], dy = S.od[4], dz = S.od[5];
    float dnorm = sqrtf(dx * dx + dy * dy + dz * dz);
    {
        const float* db = dens + (size_t)ray * NS;
        #pragma unroll
        for (int m = 0; m < 6; m++) {
            int s = l + 32 * m;
            float tv = S.wc[s].x;
            float dist = (s < NS - 1) ? (S.wc[s + 1].x - tv) * dnorm : 1e10f * dnorm;
            float de = db[s];
            S.u.p[s] = __expf(-de * dist) + 1e-10f;
        }
    }
    __syncwarp();

    // ---- Phase F: transmittance scan (blocked 6/lane), weights -> wc[].y ----
    float ad = 0.f, ao = 0.f;
    {
        float q[6], al[6];
        #pragma unroll
        for (int m = 0; m < 6; m++) {
            float pp = S.u.p[6 * l + m];
            al[m] = 1.0f - pp;                    // alpha (to ~1e-10 abs)
            q[m] = (m == 0) ? pp : q[m - 1] * pp; // in-lane inclusive products
        }
        float scn = q[5];
        #pragma unroll
        for (int o = 1; o < 32; o <<= 1) {
            float t2 = __shfl_up_sync(FULL, scn, o);
            if (l >= o) scn *= t2;
        }
        float ex = __shfl_up_sync(FULL, scn, 1);
        float pref = (l == 0) ? 1.f : ex;
        #pragma unroll
        for (int m = 0; m < 6; m++) {
            float trans = (m == 0) ? pref : pref * q[m - 1];
            float w = al[m] * trans;
            int s = 6 * l + m;
            ad += w * S.wc[s].x;
            ao += w;
            S.wc[s].y = w;
        }
    }
    __syncwarp();

    // ---- Phase G: float4 fine_points store + color accumulation ----
    float ox = S.od[0], oy = S.od[1], oz = S.od[2];
    const float4* col4 = reinterpret_cast<const float4*>(col + (size_t)ray * (NS * 3));
    float4*       out4 = reinterpret_cast<float4*>(out + (size_t)5 * N + (size_t)ray * (NS * 3));
    float ar = 0.f, ag = 0.f, ab = 0.f;

    #pragma unroll
    for (int k = 0; k < 5; k++) {
        int i4 = l + 32 * k;
        if (k < 4 || i4 < (NS * 3) / 4) {        // 144 float4s; k<4 always valid
            int e  = i4 * 4;
            int s0 = e / 3;
            int c0 = e - 3 * s0;
            float2 wcA = S.wc[s0];
            float2 wcB = S.wc[s0 + 1];           // s0 max = 190 -> safe
            float4 cvv = col4[i4];
            float ce[4] = {cvv.x, cvv.y, cvv.z, cvv.w};
            float pe[4];
            #pragma unroll
            for (int j = 0; j < 4; j++) {
                int c = c0 + j;
                float2 wc = wcA;
                if (c >= 3) { c -= 3; wc = wcB; }
                float oc = (c == 0) ? ox : ((c == 1) ? oy : oz);
                float dc = (c == 0) ? dx : ((c == 1) ? dy : dz);
                pe[j] = fmaf(dc, wc.x, oc);
                float contrib = wc.y * ce[j];
                if (c == 0)      ar += contrib;
                else if (c == 1) ag += contrib;
                else             ab += contrib;
            }
            out4[i4] = make_float4(pe[0], pe[1], pe[2], pe[3]);
        }
    }

    // ---- warp reduction + outputs ----
    #pragma unroll
    for (int o = 16; o > 0; o >>= 1) {
        ar += __shfl_xor_sync(FULL, ar, o);
        ag += __shfl_xor_sync(FULL, ag, o);
        ab += __shfl_xor_sync(FULL, ab, o);
        ad += __shfl_xor_sync(FULL, ad, o);
        ao += __shfl_xor_sync(FULL, ao, o);
    }
    if (l == 0) {
        out[(size_t)ray * 3 + 0] = ar;
        out[(size_t)ray * 3 + 1] = ag;
        out[(size_t)ray * 3 + 2] = ab;
        out[(size_t)3 * N + ray] = ad;
        out[(size_t)4 * N + ray] = ao;
    }
}

extern "C" void kernel_launch(void* const* d_in, const int* in_sizes, int n_in,
                              void* d_out, int out_size)
{
    const float* ro  = (const float*)d_in[0];
    const float* rd  = (const float*)d_in[1];
    const float* cw  = (const float*)d_in[2];
    const float* ct  = (const float*)d_in[3];
    const float* uu  = (const float*)d_in[4];
    const float* col = (const float*)d_in[5];
    const float* de  = (const float*)d_in[6];
    int N = in_sizes[0] / 3;
    nerf_kernel<<<(N + RPB - 1) / RPB, T>>>(ro, rd, cw, ct, uu, col, de, (float*)d_out, N);
}